// round 10
// baseline (speedup 1.0000x reference)
#include <cuda_runtime.h>
#include <math.h>

#define N_NODES 50000
#define KN 32
#define D 128
#define TBL 2048
#define GRID_MAIN 1368   // 152 SMs * 9 resident blocks: persistent grid-stride

__device__ __align__(16) float g_u1[D];    // W1 @ W4
__device__ __align__(16) float g_u2[D];    // W2 @ W4
__device__ float g_tbl[TBL];               // c(x) = sum_e sigmoid(x*W3[e])*W4[e]

// ---------------------------------------------------------------------------
// Precompute (all warp-parallel, coalesced):
//   blocks 0..31   : warp w computes u1/u2 row r = b*4+w (lane-strided dot)
//   blocks 32..543 : warp w computes table entry j = (b-32)*4+w
// ---------------------------------------------------------------------------
__global__ void precompute_kernel(const float* __restrict__ W1,
                                  const float* __restrict__ W2,
                                  const float* __restrict__ W3,
                                  const float* __restrict__ W4) {
    const unsigned FULL = 0xffffffffu;
    const int b = blockIdx.x;
    const int warp = threadIdx.x >> 5;
    const int lane = threadIdx.x & 31;

    if (b < 32) {
        int r = b * 4 + warp;
        float s1 = 0.0f, s2 = 0.0f;
        #pragma unroll
        for (int i = 0; i < 4; i++) {
            int e = lane + i * 32;
            float w4 = W4[e];
            s1 = fmaf(W1[r * D + e], w4, s1);
            s2 = fmaf(W2[r * D + e], w4, s2);
        }
        #pragma unroll
        for (int o = 16; o; o >>= 1) {
            s1 += __shfl_xor_sync(FULL, s1, o);
            s2 += __shfl_xor_sync(FULL, s2, o);
        }
        if (lane == 0) { g_u1[r] = s1; g_u2[r] = s2; }
    } else {
        int j = (b - 32) * 4 + warp;
        if (j < TBL) {
            float x = (float)j * (1.0f / (float)(TBL - 1));
            float s = 0.0f;
            #pragma unroll
            for (int i = 0; i < 4; i++) {
                int e = lane + i * 32;
                float z = x * W3[e];
                float sig = 1.0f / (1.0f + __expf(-z));
                s = fmaf(sig, W4[e], s);
            }
            #pragma unroll
            for (int o = 16; o; o >>= 1) s += __shfl_xor_sync(FULL, s, o);
            if (lane == 0) g_tbl[j] = s;
        }
    }
}

// ---------------------------------------------------------------------------
// Main kernel: persistent grid-stride blocks (128 threads), one node per
// iteration. Warp w owns rows [8w,8w+8), lane l owns cols [4l,4l+4). The
// register tile v[8] is dead after the weighted sum, so the NEXT node's
// loads (8x LDG.128 + self + dt) are issued there — overlapping the epilogue
// stores, barriers, and the next score phase. Two barriers per node.
// ---------------------------------------------------------------------------
__global__ __launch_bounds__(128, 9) void attn_agg_kernel(
    const float* __restrict__ self_vecs,   // [N, D]
    const float* __restrict__ neigh,       // [N, K, D]
    const float* __restrict__ dt,          // [N, K]
    const float* __restrict__ b4,          // [1]
    float* __restrict__ out,               // [N, D]
    float* __restrict__ score_out)         // [N, K]
{
    const int t = threadIdx.x;
    const int warp = t >> 5;
    const int lane = t & 31;
    const unsigned FULL = 0xffffffffu;

    __shared__ __align__(16) float partial[4][D];  // warp-partial weighted sums
    __shared__ float sc[KN];                       // relu scores

    const float4 u1v = *reinterpret_cast<const float4*>(&g_u1[lane * 4]);
    const float4 u2v = *reinterpret_cast<const float4*>(&g_u2[lane * 4]);
    const float bias = b4[0];

    // ---- prologue: load tile + self + dt for first node ---------------------
    int n = blockIdx.x;
    const int row_off = warp * (8 * 32) + lane;    // float4 offset within tile

    float4 v[8];
    {
        const float4* base =
            reinterpret_cast<const float4*>(neigh + (size_t)n * KN * D) + row_off;
        #pragma unroll
        for (int kk = 0; kk < 8; kk++) v[kk] = __ldcs(base + kk * 32);
    }
    float4 sv = *reinterpret_cast<const float4*>(
                    self_vecs + (size_t)n * D + lane * 4);
    float x_dt = (lane < 8) ? dt[(size_t)n * KN + warp * 8 + lane] : 0.0f;

    while (true) {
        // ---- a = self · u1 (per-warp redundant) -----------------------------
        float a = sv.x * u1v.x + sv.y * u1v.y + sv.z * u1v.z + sv.w * u1v.w;
        #pragma unroll
        for (int o = 16; o; o >>= 1) a += __shfl_xor_sync(FULL, a, o);
        const float ab = a + bias;

        // ---- dt -> c via table (lanes 0..7 own one row each) ----------------
        float c_lane = 0.0f;
        if (lane < 8) {
            float x = fminf(fmaxf(x_dt, 0.0f), 1.0f);
            float xf = x * (float)(TBL - 1);
            int   i0 = (int)xf;
            if (i0 > TBL - 2) i0 = TBL - 2;
            float f = xf - (float)i0;
            c_lane = g_tbl[i0] + f * (g_tbl[i0 + 1] - g_tbl[i0]);
        }

        // ---- scores for this warp's 8 rows ----------------------------------
        float s_save = 0.0f;
        #pragma unroll
        for (int kk = 0; kk < 8; kk++) {
            float p = v[kk].x * u2v.x + v[kk].y * u2v.y +
                      v[kk].z * u2v.z + v[kk].w * u2v.w;
            #pragma unroll
            for (int o = 16; o; o >>= 1) p += __shfl_xor_sync(FULL, p, o);
            float c = __shfl_sync(FULL, c_lane, kk);
            float s = fmaxf(ab + p + c, 0.0f);      // relu (warp-uniform)
            if (lane == kk) s_save = s;
        }
        if (lane < 8) sc[warp * 8 + lane] = s_save;
        __syncthreads();

        // ---- softmax over 32, redundantly in every warp ----------------------
        float s_l = sc[lane];
        float M = s_l;
        #pragma unroll
        for (int o = 16; o; o >>= 1)
            M = fmaxf(M, __shfl_xor_sync(FULL, M, o));
        float e_l = __expf(s_l - M);
        float Z = e_l;
        #pragma unroll
        for (int o = 16; o; o >>= 1) Z += __shfl_xor_sync(FULL, Z, o);
        float w_l = e_l * (1.0f / Z);

        if (t < KN) __stcs(&score_out[(size_t)n * KN + t], w_l);

        // ---- weighted neighbor sum (LAST use of v) ---------------------------
        float4 acc = make_float4(0.f, 0.f, 0.f, 0.f);
        #pragma unroll
        for (int kk = 0; kk < 8; kk++) {
            float w = __shfl_sync(FULL, w_l, warp * 8 + kk);
            acc.x = fmaf(w, v[kk].x, acc.x);
            acc.y = fmaf(w, v[kk].y, acc.y);
            acc.z = fmaf(w, v[kk].z, acc.z);
            acc.w = fmaf(w, v[kk].w, acc.w);
        }

        // ---- prefetch next node's tile + self + dt (v is dead) ---------------
        const int n_next = n + GRID_MAIN;
        const bool more = (n_next < N_NODES);
        if (more) {
            const float4* base = reinterpret_cast<const float4*>(
                                     neigh + (size_t)n_next * KN * D) + row_off;
            #pragma unroll
            for (int kk = 0; kk < 8; kk++) v[kk] = __ldcs(base + kk * 32);
            sv = *reinterpret_cast<const float4*>(
                     self_vecs + (size_t)n_next * D + lane * 4);
            if (lane < 8) x_dt = dt[(size_t)n_next * KN + warp * 8 + lane];
        }

        // ---- epilogue: combine warp partials, write out ----------------------
        *reinterpret_cast<float4*>(&partial[warp][lane * 4]) = acc;
        __syncthreads();
        __stcs(&out[(size_t)n * D + t],
               partial[0][t] + partial[1][t] + partial[2][t] + partial[3][t]);

        if (!more) break;
        n = n_next;
    }
}

// ---------------------------------------------------------------------------
// Launch
// ---------------------------------------------------------------------------
extern "C" void kernel_launch(void* const* d_in, const int* in_sizes, int n_in,
                              void* d_out, int out_size) {
    const float* self_vecs = (const float*)d_in[0];  // [N, 128]
    const float* neigh     = (const float*)d_in[1];  // [N, 32, 128]
    const float* dt        = (const float*)d_in[2];  // [N, 32]
    const float* W1        = (const float*)d_in[3];  // [128, 128]
    const float* W2        = (const float*)d_in[4];  // [128, 128]
    const float* W3        = (const float*)d_in[5];  // [1, 128]
    const float* W4        = (const float*)d_in[6];  // [128, 1]
    const float* b4        = (const float*)d_in[7];  // [1]

    float* out   = (float*)d_out;                      // [N, 128] first
    float* score = out + (size_t)N_NODES * D;          // then [N, 32]

    precompute_kernel<<<32 + TBL / 4, 128>>>(W1, W2, W3, W4);
    attn_agg_kernel<<<GRID_MAIN, 128>>>(self_vecs, neigh, dt, b4, out, score);
}

// round 11
// speedup vs baseline: 1.2647x; 1.2647x over previous
#include <cuda_runtime.h>
#include <math.h>

#define N_NODES 50000
#define KN 32
#define D 128
#define TBL 2048

__device__ __align__(16) float g_u1[D];    // W1 @ W4
__device__ __align__(16) float g_u2[D];    // W2 @ W4
__device__ float g_tbl[TBL];               // c(x) = sum_e sigmoid(x*W3[e])*W4[e]

// ---------------------------------------------------------------------------
// Precompute (all warp-parallel, coalesced):
//   blocks 0..31   : warp w computes u1/u2 row r = b*4+w (lane-strided dot)
//   blocks 32..543 : warp w computes table entry j = (b-32)*4+w
// ---------------------------------------------------------------------------
__global__ void precompute_kernel(const float* __restrict__ W1,
                                  const float* __restrict__ W2,
                                  const float* __restrict__ W3,
                                  const float* __restrict__ W4) {
    const unsigned FULL = 0xffffffffu;
    const int b = blockIdx.x;
    const int warp = threadIdx.x >> 5;
    const int lane = threadIdx.x & 31;

    if (b < 32) {
        int r = b * 4 + warp;
        float s1 = 0.0f, s2 = 0.0f;
        #pragma unroll
        for (int i = 0; i < 4; i++) {
            int e = lane + i * 32;
            float w4 = W4[e];
            s1 = fmaf(W1[r * D + e], w4, s1);
            s2 = fmaf(W2[r * D + e], w4, s2);
        }
        #pragma unroll
        for (int o = 16; o; o >>= 1) {
            s1 += __shfl_xor_sync(FULL, s1, o);
            s2 += __shfl_xor_sync(FULL, s2, o);
        }
        if (lane == 0) { g_u1[r] = s1; g_u2[r] = s2; }
    } else {
        int j = (b - 32) * 4 + warp;
        if (j < TBL) {
            float x = (float)j * (1.0f / (float)(TBL - 1));
            float s = 0.0f;
            #pragma unroll
            for (int i = 0; i < 4; i++) {
                int e = lane + i * 32;
                float z = x * W3[e];
                float sig = 1.0f / (1.0f + __expf(-z));
                s = fmaf(sig, W4[e], s);
            }
            #pragma unroll
            for (int o = 16; o; o >>= 1) s += __shfl_xor_sync(FULL, s, o);
            if (lane == 0) g_tbl[j] = s;
        }
    }
}

// ---------------------------------------------------------------------------
// Main kernel: one block (128 threads) per node. Neighbor tile in REGISTERS
// (warp w owns rows [8w,8w+8), lane l owns cols [4l,4l+4)), all global reads
// front-batched for max MLP. Self-dot split across warps (scalar per thread,
// combined via smem after the barrier; relu applied post-barrier) to trim
// registers to <=48 -> 10 resident blocks/SM.
// ---------------------------------------------------------------------------
__global__ __launch_bounds__(128, 10) void attn_agg_kernel(
    const float* __restrict__ self_vecs,   // [N, D]
    const float* __restrict__ neigh,       // [N, K, D]
    const float* __restrict__ dt,          // [N, K]
    const float* __restrict__ b4,          // [1]
    float* __restrict__ out,               // [N, D]
    float* __restrict__ score_out)         // [N, K]
{
    const int n = blockIdx.x;
    const int t = threadIdx.x;
    const int warp = t >> 5;
    const int lane = t & 31;
    const unsigned FULL = 0xffffffffu;

    __shared__ __align__(16) float partial[4][D];  // warp-partial weighted sums
    __shared__ float sc[KN];                       // p + c (pre-relu, pre-ab)
    __shared__ float red[4];                       // self-dot warp partials

    // ---- front-batch ALL global reads (8x LDG.128 + self + dt) -------------
    const float4* __restrict__ base =
        reinterpret_cast<const float4*>(neigh + (size_t)n * KN * D) +
        warp * (8 * 32) + lane;
    float4 v[8];
    #pragma unroll
    for (int kk = 0; kk < 8; kk++) v[kk] = __ldcs(base + kk * 32);

    const float sv = self_vecs[(size_t)n * D + t];     // scalar, coalesced
    float x_dt = 0.0f;
    if (lane < 8) x_dt = dt[(size_t)n * KN + warp * 8 + lane];

    // ---- self-dot partial: warp w covers elems [32w,32w+32) -----------------
    float ap = sv * g_u1[t];
    #pragma unroll
    for (int o = 16; o; o >>= 1) ap += __shfl_xor_sync(FULL, ap, o);
    if (lane == 0) red[warp] = ap;

    // ---- dt -> c via table (lanes 0..7 own one row each) --------------------
    float c_lane = 0.0f;
    if (lane < 8) {
        float x = fminf(fmaxf(x_dt, 0.0f), 1.0f);
        float xf = x * (float)(TBL - 1);
        int   i0 = (int)xf;
        if (i0 > TBL - 2) i0 = TBL - 2;
        float f = xf - (float)i0;
        c_lane = g_tbl[i0] + f * (g_tbl[i0 + 1] - g_tbl[i0]);
    }

    // ---- pre-scores (p + c) for this warp's 8 rows ---------------------------
    const float4 u2v = *reinterpret_cast<const float4*>(&g_u2[lane * 4]);
    float s_save = 0.0f;
    #pragma unroll
    for (int kk = 0; kk < 8; kk++) {
        float p = v[kk].x * u2v.x + v[kk].y * u2v.y +
                  v[kk].z * u2v.z + v[kk].w * u2v.w;
        #pragma unroll
        for (int o = 16; o; o >>= 1) p += __shfl_xor_sync(FULL, p, o);
        float c = __shfl_sync(FULL, c_lane, kk);
        if (lane == kk) s_save = p + c;
    }
    if (lane < 8) sc[warp * 8 + lane] = s_save;
    __syncthreads();

    // ---- ab + relu + softmax over 32, redundantly in every warp --------------
    const float ab = red[0] + red[1] + red[2] + red[3] + b4[0];
    float s_l = fmaxf(ab + sc[lane], 0.0f);           // relu here (identical math)
    float M = s_l;
    #pragma unroll
    for (int o = 16; o; o >>= 1)
        M = fmaxf(M, __shfl_xor_sync(FULL, M, o));
    float e_l = __expf(s_l - M);
    float Z = e_l;
    #pragma unroll
    for (int o = 16; o; o >>= 1) Z += __shfl_xor_sync(FULL, Z, o);
    float w_l = e_l * (1.0f / Z);

    if (t < KN) __stcs(&score_out[(size_t)n * KN + t], w_l);  // warp 0 writes

    // ---- weighted neighbor sum from registers --------------------------------
    float4 acc = make_float4(0.f, 0.f, 0.f, 0.f);
    #pragma unroll
    for (int kk = 0; kk < 8; kk++) {
        float w = __shfl_sync(FULL, w_l, warp * 8 + kk);
        acc.x = fmaf(w, v[kk].x, acc.x);
        acc.y = fmaf(w, v[kk].y, acc.y);
        acc.z = fmaf(w, v[kk].z, acc.z);
        acc.w = fmaf(w, v[kk].w, acc.w);
    }
    *reinterpret_cast<float4*>(&partial[warp][lane * 4]) = acc;
    __syncthreads();

    __stcs(&out[(size_t)n * D + t],
           partial[0][t] + partial[1][t] + partial[2][t] + partial[3][t]);
}

// ---------------------------------------------------------------------------
// Launch
// ---------------------------------------------------------------------------
extern "C" void kernel_launch(void* const* d_in, const int* in_sizes, int n_in,
                              void* d_out, int out_size) {
    const float* self_vecs = (const float*)d_in[0];  // [N, 128]
    const float* neigh     = (const float*)d_in[1];  // [N, 32, 128]
    const float* dt        = (const float*)d_in[2];  // [N, 32]
    const float* W1        = (const float*)d_in[3];  // [128, 128]
    const float* W2        = (const float*)d_in[4];  // [128, 128]
    const float* W3        = (const float*)d_in[5];  // [1, 128]
    const float* W4        = (const float*)d_in[6];  // [128, 1]
    const float* b4        = (const float*)d_in[7];  // [1]

    float* out   = (float*)d_out;                      // [N, 128] first
    float* score = out + (size_t)N_NODES * D;          // then [N, 32]

    precompute_kernel<<<32 + TBL / 4, 128>>>(W1, W2, W3, W4);
    attn_agg_kernel<<<N_NODES, 128>>>(self_vecs, neigh, dt, b4, out, score);
}

// round 12
// speedup vs baseline: 1.4343x; 1.1341x over previous
#include <cuda_runtime.h>
#include <math.h>

#define N_NODES 50000
#define KN 32
#define D 128
#define TBL 2048

__device__ __align__(16) float g_u1[D];    // W1 @ W4
__device__ __align__(16) float g_u2[D];    // W2 @ W4
__device__ float g_tbl[TBL];               // c(x) = sum_e sigmoid(x*W3[e])*W4[e]

// ---------------------------------------------------------------------------
// Precompute (all warp-parallel, coalesced):
//   blocks 0..31   : warp w computes u1/u2 row r = b*4+w (lane-strided dot)
//   blocks 32..543 : warp w computes table entry j = (b-32)*4+w
// ---------------------------------------------------------------------------
__global__ void precompute_kernel(const float* __restrict__ W1,
                                  const float* __restrict__ W2,
                                  const float* __restrict__ W3,
                                  const float* __restrict__ W4) {
    const unsigned FULL = 0xffffffffu;
    const int b = blockIdx.x;
    const int warp = threadIdx.x >> 5;
    const int lane = threadIdx.x & 31;

    if (b < 32) {
        int r = b * 4 + warp;
        float s1 = 0.0f, s2 = 0.0f;
        #pragma unroll
        for (int i = 0; i < 4; i++) {
            int e = lane + i * 32;
            float w4 = W4[e];
            s1 = fmaf(W1[r * D + e], w4, s1);
            s2 = fmaf(W2[r * D + e], w4, s2);
        }
        #pragma unroll
        for (int o = 16; o; o >>= 1) {
            s1 += __shfl_xor_sync(FULL, s1, o);
            s2 += __shfl_xor_sync(FULL, s2, o);
        }
        if (lane == 0) { g_u1[r] = s1; g_u2[r] = s2; }
    } else {
        int j = (b - 32) * 4 + warp;
        if (j < TBL) {
            float x = (float)j * (1.0f / (float)(TBL - 1));
            float s = 0.0f;
            #pragma unroll
            for (int i = 0; i < 4; i++) {
                int e = lane + i * 32;
                float z = x * W3[e];
                float sig = 1.0f / (1.0f + __expf(-z));
                s = fmaf(sig, W4[e], s);
            }
            #pragma unroll
            for (int o = 16; o; o >>= 1) s += __shfl_xor_sync(FULL, s, o);
            if (lane == 0) g_tbl[j] = s;
        }
    }
}

// ---------------------------------------------------------------------------
// Main kernel: one block (128 threads) per node. Neighbor tile in REGISTERS
// (warp w owns rows [8w,8w+8), lane l owns cols [4l,4l+4)), all global reads
// front-batched for max MLP. Two barriers total.
// ---------------------------------------------------------------------------
__global__ __launch_bounds__(128, 9) void attn_agg_kernel(
    const float* __restrict__ self_vecs,   // [N, D]
    const float* __restrict__ neigh,       // [N, K, D]
    const float* __restrict__ dt,          // [N, K]
    const float* __restrict__ b4,          // [1]
    float* __restrict__ out,               // [N, D]
    float* __restrict__ score_out)         // [N, K]
{
    const int n = blockIdx.x;
    const int t = threadIdx.x;
    const int warp = t >> 5;
    const int lane = t & 31;
    const unsigned FULL = 0xffffffffu;

    __shared__ __align__(16) float partial[4][D];  // warp-partial weighted sums
    __shared__ float sc[KN];                       // relu scores

    // ---- front-batch ALL global reads (8x LDG.128 + self + dt) -------------
    const float4* __restrict__ base =
        reinterpret_cast<const float4*>(neigh + (size_t)n * KN * D) +
        warp * (8 * 32) + lane;
    float4 v[8];
    #pragma unroll
    for (int kk = 0; kk < 8; kk++) v[kk] = __ldcs(base + kk * 32);

    const float4 sv = *reinterpret_cast<const float4*>(
                          self_vecs + (size_t)n * D + lane * 4);
    float x_dt = 0.0f;
    if (lane < 8) x_dt = dt[(size_t)n * KN + warp * 8 + lane];

    // ---- a = self · u1 (per-warp redundant, no block sync) ------------------
    const float4 u1v = *reinterpret_cast<const float4*>(&g_u1[lane * 4]);
    const float4 u2v = *reinterpret_cast<const float4*>(&g_u2[lane * 4]);
    float a = sv.x * u1v.x + sv.y * u1v.y + sv.z * u1v.z + sv.w * u1v.w;
    #pragma unroll
    for (int o = 16; o; o >>= 1) a += __shfl_xor_sync(FULL, a, o);
    const float ab = a + b4[0];

    // ---- dt -> c via table (lanes 0..7 own one row each) --------------------
    float c_lane = 0.0f;
    if (lane < 8) {
        float x = fminf(fmaxf(x_dt, 0.0f), 1.0f);
        float xf = x * (float)(TBL - 1);
        int   i0 = (int)xf;
        if (i0 > TBL - 2) i0 = TBL - 2;
        float f = xf - (float)i0;
        c_lane = g_tbl[i0] + f * (g_tbl[i0 + 1] - g_tbl[i0]);
    }

    // ---- scores for this warp's 8 rows --------------------------------------
    float s_save = 0.0f;
    #pragma unroll
    for (int kk = 0; kk < 8; kk++) {
        float p = v[kk].x * u2v.x + v[kk].y * u2v.y +
                  v[kk].z * u2v.z + v[kk].w * u2v.w;
        #pragma unroll
        for (int o = 16; o; o >>= 1) p += __shfl_xor_sync(FULL, p, o);
        float c = __shfl_sync(FULL, c_lane, kk);
        float s = fmaxf(ab + p + c, 0.0f);          // relu (warp-uniform)
        if (lane == kk) s_save = s;
    }
    if (lane < 8) sc[warp * 8 + lane] = s_save;
    __syncthreads();

    // ---- softmax over 32, redundantly in every warp --------------------------
    float s_l = sc[lane];
    float M = s_l;
    #pragma unroll
    for (int o = 16; o; o >>= 1)
        M = fmaxf(M, __shfl_xor_sync(FULL, M, o));
    float e_l = __expf(s_l - M);
    float Z = e_l;
    #pragma unroll
    for (int o = 16; o; o >>= 1) Z += __shfl_xor_sync(FULL, Z, o);
    float w_l = e_l * (1.0f / Z);

    if (t < KN) __stcs(&score_out[(size_t)n * KN + t], w_l);  // warp 0 writes

    // ---- weighted neighbor sum from registers --------------------------------
    float4 acc = make_float4(0.f, 0.f, 0.f, 0.f);
    #pragma unroll
    for (int kk = 0; kk < 8; kk++) {
        float w = __shfl_sync(FULL, w_l, warp * 8 + kk);
        acc.x = fmaf(w, v[kk].x, acc.x);
        acc.y = fmaf(w, v[kk].y, acc.y);
        acc.z = fmaf(w, v[kk].z, acc.z);
        acc.w = fmaf(w, v[kk].w, acc.w);
    }
    *reinterpret_cast<float4*>(&partial[warp][lane * 4]) = acc;
    __syncthreads();

    __stcs(&out[(size_t)n * D + t],
           partial[0][t] + partial[1][t] + partial[2][t] + partial[3][t]);
}

// ---------------------------------------------------------------------------
// Launch
// ---------------------------------------------------------------------------
extern "C" void kernel_launch(void* const* d_in, const int* in_sizes, int n_in,
                              void* d_out, int out_size) {
    const float* self_vecs = (const float*)d_in[0];  // [N, 128]
    const float* neigh     = (const float*)d_in[1];  // [N, 32, 128]
    const float* dt        = (const float*)d_in[2];  // [N, 32]
    const float* W1        = (const float*)d_in[3];  // [128, 128]
    const float* W2        = (const float*)d_in[4];  // [128, 128]
    const float* W3        = (const float*)d_in[5];  // [1, 128]
    const float* W4        = (const float*)d_in[6];  // [128, 1]
    const float* b4        = (const float*)d_in[7];  // [1]

    float* out   = (float*)d_out;                      // [N, 128] first
    float* score = out + (size_t)N_NODES * D;          // then [N, 32]

    precompute_kernel<<<32 + TBL / 4, 128>>>(W1, W2, W3, W4);
    attn_agg_kernel<<<N_NODES, 128>>>(self_vecs, neigh, dt, b4, out, score);
}